// round 16
// baseline (speedup 1.0000x reference)
#include <cuda_runtime.h>
#include <cuda_bf16.h>

// PointMatcher: pred (N=1024,20,2) vs gt (M=2048,20,2)
// dist(i,j) = mean_p ||pred[i,p]-gt[j,p]|| ; argmin over j per i.
// R15 core + M split in 4 chunks/group for wave balance (grid 1024).
// Cross-CTA merge: atomicMax of ~key into zero-init __device__ scratch
// (complement => zero-init is identity; idempotent across graph replays).
// Last-arriving CTA per group writes outputs (fence + counter idiom).
// Outputs concatenated in d_out (float32):
//   [0..N*40) matched gt rows | [N*40..N*41) confidence | [N*41..N*42) indices

#define BI      4
#define NCHUNK  4                           // M-chunks per pred group
#define TJ      256
#define NTILES  2                           // (M/NCHUNK)/TJ
#define P       20
#define ROWF    40
#define THREADS 1024
#define TILEF   (TJ * ROWF)                 // 10240 floats
#define TILEB   (TILEF * 4)                 // 40960 bytes
#define SMEM_BYTES (2*TILEB + BI*8 + 2*8 + 16)
#define NMAX    1024

typedef unsigned long long ull;

__device__ ull g_best[NMAX];                // zero-init; holds max(~key)
__device__ unsigned g_cnt[NMAX / BI];       // zero-init arrival counters

__device__ __forceinline__ float fsqrt_approx(float x) {
    float r;
    asm("sqrt.approx.f32 %0, %1;" : "=f"(r) : "f"(x));
    return r;
}
__device__ __forceinline__ void mbar_init(unsigned mbar, unsigned cnt) {
    asm volatile("mbarrier.init.shared.b64 [%0], %1;" :: "r"(mbar), "r"(cnt) : "memory");
}
__device__ __forceinline__ void mbar_expect_tx(unsigned mbar, unsigned bytes) {
    asm volatile("mbarrier.arrive.expect_tx.shared.b64 _, [%0], %1;"
                 :: "r"(mbar), "r"(bytes) : "memory");
}
__device__ __forceinline__ void bulk_ld(unsigned dst, const void* src,
                                        unsigned bytes, unsigned mbar) {
    asm volatile(
        "cp.async.bulk.shared::cluster.global.mbarrier::complete_tx::bytes "
        "[%0], [%1], %2, [%3];"
        :: "r"(dst), "l"(src), "r"(bytes), "r"(mbar) : "memory");
}
__device__ __forceinline__ void mbar_wait(unsigned mbar, unsigned phase) {
    asm volatile(
        "{\n\t.reg .pred P1;\n\t"
        "W_%=:\n\t"
        "mbarrier.try_wait.parity.acquire.cta.shared::cta.b64 P1, [%0], %1, 0x989680;\n\t"
        "@P1 bra D_%=;\n\t"
        "bra W_%=;\n\t"
        "D_%=:\n\t}"
        :: "r"(mbar), "r"(phase) : "memory");
}

__global__ __launch_bounds__(THREADS, 2)
void pointmatcher_kernel(const float* __restrict__ pred,
                         const float* __restrict__ gt,
                         float* __restrict__ out_mp,
                         float* __restrict__ out_conf,
                         float* __restrict__ out_idx,
                         int N, int M)
{
    extern __shared__ __align__(16) float smem[];
    float* buf0 = smem;
    float* buf1 = smem + TILEF;
    ull*   best = (ull*)(smem + 2 * TILEF);
    int*   lastf = (int*)(best + BI + 1);           // after mbar slots
    unsigned mbar0 = (unsigned)__cvta_generic_to_shared(best + BI);
    unsigned mbar1 = mbar0 + 8;

    const int tid   = threadIdx.x;
    const int il    = tid & 3;           // pred row within group
    const int pq    = (tid >> 2) & 3;    // point quarter (partners lane^4,^8)
    const int jl    = tid >> 4;          // 0..63 -> rows jl+{0,64,128,192}
    const int grp   = blockIdx.y;        // pred group (0..255)
    const int i     = grp * BI + il;
    const int jbase = blockIdx.x * (TJ * NTILES);   // chunk start (0/512/1024/1536)

    if (tid < BI) best[tid] = ~0ull;
    if (tid == 0) { mbar_init(mbar0, 1); mbar_init(mbar1, 1); }

    // Pred points owned by this pq: {4pq..4pq+3} and {16+pq}. Plain scalars.
    float px0, py0, px1, py1, px2, py2, px3, py3, px4, py4;
    {
        const float2* p2 = (const float2*)(pred + (size_t)i * ROWF);
        float2 v;
        v = p2[4 * pq];     px0 = v.x; py0 = v.y;
        v = p2[4 * pq + 1]; px1 = v.x; py1 = v.y;
        v = p2[4 * pq + 2]; px2 = v.x; py2 = v.y;
        v = p2[4 * pq + 3]; px3 = v.x; py3 = v.y;
        v = p2[16 + pq];    px4 = v.x; py4 = v.y;
    }

    __syncthreads();                     // mbarrier init + best[] visible
    if (tid == 0) {                      // prefetch tile 0 of this chunk
        mbar_expect_tx(mbar0, TILEB);
        bulk_ld((unsigned)__cvta_generic_to_shared(buf0),
                gt + (size_t)jbase * ROWF, TILEB, mbar0);
    }

    float minv = 3.402823466e+38f;       // min of SUM over P (mean deferred)
    int   minj = 0;

    #pragma unroll
    for (int t = 0; t < NTILES; t++) {
        unsigned mb = (t & 1) ? mbar1 : mbar0;
        mbar_wait(mb, 0);                // tile t landed (each mbar used once)
        __syncthreads();

        if (tid == 0 && t + 1 < NTILES) {
            mbar_expect_tx(mbar1, TILEB);
            bulk_ld((unsigned)__cvta_generic_to_shared(buf1),
                    gt + (size_t)(jbase + TJ) * ROWF, TILEB, mbar1);
        }

        const float* tb = (t & 1) ? buf1 : buf0;
        const float* base = tb + jl * ROWF;
        float s0, s1, s2, s3;

        #pragma unroll
        for (int r = 0; r < 4; r++) {    // rows jl + 64*r
            const float* rb = base + r * 64 * ROWF;
            float4 a = *(const float4*)(rb + 8 * pq);       // pts 4pq,4pq+1
            float4 b = *(const float4*)(rb + 8 * pq + 4);   // pts 4pq+2,4pq+3
            float2 c = *(const float2*)(rb + 32 + 2 * pq);  // pt 16+pq
            float dx, dy, acc;
            dx = a.x - px0; dy = a.y - py0;
            acc  = fsqrt_approx(fmaf(dx, dx, dy * dy));
            dx = a.z - px1; dy = a.w - py1;
            acc += fsqrt_approx(fmaf(dx, dx, dy * dy));
            dx = b.x - px2; dy = b.y - py2;
            acc += fsqrt_approx(fmaf(dx, dx, dy * dy));
            dx = b.z - px3; dy = b.w - py3;
            acc += fsqrt_approx(fmaf(dx, dx, dy * dy));
            dx = c.x - px4; dy = c.y - py4;
            acc += fsqrt_approx(fmaf(dx, dx, dy * dy));
            if (r == 0) s0 = acc;
            else if (r == 1) s1 = acc;
            else if (r == 2) s2 = acc;
            else s3 = acc;
        }

        // Butterfly-combine the 4 point-quarters (same il, jl).
        s0 += __shfl_xor_sync(0xffffffffu, s0, 4);
        s0 += __shfl_xor_sync(0xffffffffu, s0, 8);
        s1 += __shfl_xor_sync(0xffffffffu, s1, 4);
        s1 += __shfl_xor_sync(0xffffffffu, s1, 8);
        s2 += __shfl_xor_sync(0xffffffffu, s2, 4);
        s2 += __shfl_xor_sync(0xffffffffu, s2, 8);
        s3 += __shfl_xor_sync(0xffffffffu, s3, 4);
        s3 += __shfl_xor_sync(0xffffffffu, s3, 8);

        int jb = jbase + t * TJ + jl;
        if (s0 < minv) { minv = s0; minj = jb;       }  // ascending j order:
        if (s1 < minv) { minv = s1; minj = jb + 64;  }  // strict '<' keeps
        if (s2 < minv) { minv = s2; minj = jb + 128; }  // first occurrence
        if (s3 < minv) { minv = s3; minj = jb + 192; }
    }

    // CTA-local argmin (packed key: (dist_bits<<32)|j, min = lexicographic).
    if (pq == 0) {
        ull key = ((ull)__float_as_uint(minv) << 32) | (unsigned)minj;
        atomicMin(&best[il], key);
    }
    __syncthreads();

    // Cross-CTA merge: store complement, atomicMax vs zero-init scratch.
    if (tid < BI)
        atomicMax(&g_best[grp * BI + tid], ~best[tid]);
    __threadfence();
    if (tid == 0) {
        unsigned old = atomicAdd(&g_cnt[grp], 1u);
        *lastf = ((old & (NCHUNK - 1)) == NCHUNK - 1);
    }
    __syncthreads();
    if (!*lastf) return;
    __threadfence();                      // see all chunks' g_best updates

    // Last CTA of this group writes the outputs.
    if (tid < BI) {
        ull key = ~((volatile ull*)g_best)[grp * BI + tid];
        int j = (int)(unsigned)key;
        float md = __uint_as_float((unsigned)(key >> 32)) * (1.0f / (float)P);
        int row = grp * BI + tid;
        out_conf[row] = (md > 2.0f) ? 0.0f : expf(-md);
        out_idx[row]  = (float)j;
    }
    if (tid < BI * ROWF) {
        int ilg = tid / ROWF;
        int k   = tid - ilg * ROWF;
        ull key = ~((volatile ull*)g_best)[grp * BI + ilg];
        int j   = (int)(unsigned)key;
        out_mp[(grp * BI + ilg) * ROWF + k] = gt[(size_t)j * ROWF + k];
    }
}

extern "C" void kernel_launch(void* const* d_in, const int* in_sizes, int n_in,
                              void* d_out, int out_size)
{
    const float* pred = (const float*)d_in[0];
    const float* gt   = (const float*)d_in[1];
    float* out        = (float*)d_out;

    int N = in_sizes[0] / ROWF;   // 1024
    int M = in_sizes[1] / ROWF;   // 2048

    float* out_mp   = out;
    float* out_conf = out + (size_t)N * ROWF;
    float* out_idx  = out + (size_t)N * ROWF + N;

    static bool attr_set = false;  // host-side only; not in the captured graph
    if (!attr_set) {
        cudaFuncSetAttribute(pointmatcher_kernel,
                             cudaFuncAttributeMaxDynamicSharedMemorySize,
                             SMEM_BYTES);
        attr_set = true;
    }

    dim3 grid(NCHUNK, N / BI);    // (4, 256) = 1024 CTAs
    pointmatcher_kernel<<<grid, THREADS, SMEM_BYTES>>>(
        pred, gt, out_mp, out_conf, out_idx, N, M);
}

// round 17
// speedup vs baseline: 1.1979x; 1.1979x over previous
#include <cuda_runtime.h>
#include <cuda_bf16.h>

// PointMatcher: pred (N=1024,20,2) vs gt (M=2048,20,2)
// dist(i,j) = mean_p ||pred[i,p]-gt[j,p]|| ; argmin over j per i.
// Quad-split-P: pq owns points {4pq..4pq+3} (two LDS.128) + {16+pq} (LDS.64),
// scalar f32 math. Per-tile row-sum combine is a reduce-SCATTER (3 shfls):
// lane pq ends owning the total for row jb+64*pq; each lane tracks its own
// running argmin and all lanes merge into the block argmin at the end.
// 1024-thread blocks, <=32 regs, 2 CTAs/SM. TMA bulk double-buffered tiles.
// Outputs concatenated in d_out (float32):
//   [0..N*40) matched gt rows | [N*40..N*41) confidence | [N*41..N*42) indices

#define BI      4
#define TJ      256
#define P       20
#define ROWF    40
#define THREADS 1024
#define NTILES  8                           // M/TJ
#define TILEF   (TJ * ROWF)                 // 10240 floats
#define TILEB   (TILEF * 4)                 // 40960 bytes
#define SMEM_BYTES (2*TILEB + BI*8 + 2*8)

typedef unsigned long long ull;

__device__ __forceinline__ float fsqrt_approx(float x) {
    float r;
    asm("sqrt.approx.f32 %0, %1;" : "=f"(r) : "f"(x));
    return r;
}
__device__ __forceinline__ void mbar_init(unsigned mbar, unsigned cnt) {
    asm volatile("mbarrier.init.shared.b64 [%0], %1;" :: "r"(mbar), "r"(cnt) : "memory");
}
__device__ __forceinline__ void mbar_expect_tx(unsigned mbar, unsigned bytes) {
    asm volatile("mbarrier.arrive.expect_tx.shared.b64 _, [%0], %1;"
                 :: "r"(mbar), "r"(bytes) : "memory");
}
__device__ __forceinline__ void bulk_ld(unsigned dst, const void* src,
                                        unsigned bytes, unsigned mbar) {
    asm volatile(
        "cp.async.bulk.shared::cluster.global.mbarrier::complete_tx::bytes "
        "[%0], [%1], %2, [%3];"
        :: "r"(dst), "l"(src), "r"(bytes), "r"(mbar) : "memory");
}
__device__ __forceinline__ void mbar_wait(unsigned mbar, unsigned phase) {
    asm volatile(
        "{\n\t.reg .pred P1;\n\t"
        "W_%=:\n\t"
        "mbarrier.try_wait.parity.acquire.cta.shared::cta.b64 P1, [%0], %1, 0x989680;\n\t"
        "@P1 bra D_%=;\n\t"
        "bra W_%=;\n\t"
        "D_%=:\n\t}"
        :: "r"(mbar), "r"(phase) : "memory");
}

__global__ __launch_bounds__(THREADS, 2)
void pointmatcher_kernel(const float* __restrict__ pred,
                         const float* __restrict__ gt,
                         float* __restrict__ out_mp,
                         float* __restrict__ out_conf,
                         float* __restrict__ out_idx,
                         int N, int M)
{
    extern __shared__ __align__(16) float smem[];
    float* buf0 = smem;
    float* buf1 = smem + TILEF;
    ull*   best = (ull*)(smem + 2 * TILEF);
    unsigned mbar0 = (unsigned)__cvta_generic_to_shared(best + BI);
    unsigned mbar1 = mbar0 + 8;

    const int tid = threadIdx.x;
    const int il  = tid & 3;             // pred row within block
    const int pq  = (tid >> 2) & 3;      // point quarter (lane bits 2-3)
    const int jl  = tid >> 4;            // 0..63 -> rows jl+{0,64,128,192}
    const int i   = blockIdx.x * BI + il;

    if (tid < BI) best[tid] = ~0ull;
    if (tid == 0) { mbar_init(mbar0, 1); mbar_init(mbar1, 1); }

    // Pred points owned by this pq: {4pq..4pq+3} and {16+pq}. Plain scalars.
    float px0, py0, px1, py1, px2, py2, px3, py3, px4, py4;
    {
        const float2* p2 = (const float2*)(pred + (size_t)i * ROWF);
        float2 v;
        v = p2[4 * pq];     px0 = v.x; py0 = v.y;
        v = p2[4 * pq + 1]; px1 = v.x; py1 = v.y;
        v = p2[4 * pq + 2]; px2 = v.x; py2 = v.y;
        v = p2[4 * pq + 3]; px3 = v.x; py3 = v.y;
        v = p2[16 + pq];    px4 = v.x; py4 = v.y;
    }

    __syncthreads();                     // mbarrier init + best[] visible
    if (tid == 0) {                      // prefetch tile 0: ONE bulk copy
        mbar_expect_tx(mbar0, TILEB);
        bulk_ld((unsigned)__cvta_generic_to_shared(buf0), gt, TILEB, mbar0);
    }

    float minv = 3.402823466e+38f;       // min of SUM over P (mean deferred)
    int   minj = 0;

    for (int t = 0; t < NTILES; t++) {
        unsigned mb = (t & 1) ? mbar1 : mbar0;
        mbar_wait(mb, (t >> 1) & 1);     // tile t landed
        __syncthreads();                 // all threads done with other buf

        if (tid == 0 && t + 1 < NTILES) {
            unsigned mbn = ((t + 1) & 1) ? mbar1 : mbar0;
            float* dst = ((t + 1) & 1) ? buf1 : buf0;
            mbar_expect_tx(mbn, TILEB);
            bulk_ld((unsigned)__cvta_generic_to_shared(dst),
                    gt + (size_t)(t + 1) * TILEF, TILEB, mbn);
        }

        const float* tb = (t & 1) ? buf1 : buf0;
        const float* base = tb + jl * ROWF;
        float s0, s1, s2, s3;

        #pragma unroll
        for (int r = 0; r < 4; r++) {    // rows jl + 64*r
            const float* rb = base + r * 64 * ROWF;
            float4 a = *(const float4*)(rb + 8 * pq);       // pts 4pq,4pq+1
            float4 b = *(const float4*)(rb + 8 * pq + 4);   // pts 4pq+2,4pq+3
            float2 c = *(const float2*)(rb + 32 + 2 * pq);  // pt 16+pq
            float dx, dy, acc;
            dx = a.x - px0; dy = a.y - py0;
            acc  = fsqrt_approx(fmaf(dx, dx, dy * dy));
            dx = a.z - px1; dy = a.w - py1;
            acc += fsqrt_approx(fmaf(dx, dx, dy * dy));
            dx = b.x - px2; dy = b.y - py2;
            acc += fsqrt_approx(fmaf(dx, dx, dy * dy));
            dx = b.z - px3; dy = b.w - py3;
            acc += fsqrt_approx(fmaf(dx, dx, dy * dy));
            dx = c.x - px4; dy = c.y - py4;
            acc += fsqrt_approx(fmaf(dx, dx, dy * dy));
            if (r == 0) s0 = acc;
            else if (r == 1) s1 = acc;
            else if (r == 2) s2 = acc;
            else s3 = acc;
        }

        // Reduce-scatter over the 4 pq lanes (s_k <-> row jb + 64k).
        // Round 1 (xor 4): keep k with bit0(k)==bit0(pq).
        float send0 = (pq & 1) ? s0 : s1;
        float send1 = (pq & 1) ? s2 : s3;
        float r0 = __shfl_xor_sync(0xffffffffu, send0, 4);
        float r1 = __shfl_xor_sync(0xffffffffu, send1, 4);
        float t0 = ((pq & 1) ? s1 : s0) + r0;   // k = pq&1
        float t1 = ((pq & 1) ? s3 : s2) + r1;   // k = 2|(pq&1)
        // Round 2 (xor 8): keep k with bit1(k)==bit1(pq) -> k = pq.
        float send2 = (pq & 2) ? t0 : t1;
        float r2 = __shfl_xor_sync(0xffffffffu, send2, 8);
        float tot = ((pq & 2) ? t1 : t0) + r2;

        int j = t * TJ + jl + 64 * pq;   // this lane's owned row
        if (tot < minv) { minv = tot; minj = j; }  // j ascending per thread
    }

    // Block argmin: packed (dist_bits, j); min == (min dist, then min j).
    // All lanes participate (each owns a disjoint row subset).
    {
        ull key = ((ull)__float_as_uint(minv) << 32) | (unsigned)minj;
        atomicMin(&best[il], key);
    }
    __syncthreads();

    if (tid < BI) {
        ull b = best[tid];
        int j = (int)(unsigned)b;
        float md = __uint_as_float((unsigned)(b >> 32)) * (1.0f / (float)P);
        int row  = blockIdx.x * BI + tid;
        out_conf[row] = (md > 2.0f) ? 0.0f : expf(-md);
        out_idx[row]  = (float)j;
    }
    if (tid < BI * ROWF) {
        int ilg = tid / ROWF;
        int k   = tid - ilg * ROWF;
        int j   = (int)(unsigned)best[ilg];
        out_mp[(blockIdx.x * BI + ilg) * ROWF + k] = gt[(size_t)j * ROWF + k];
    }
}

extern "C" void kernel_launch(void* const* d_in, const int* in_sizes, int n_in,
                              void* d_out, int out_size)
{
    const float* pred = (const float*)d_in[0];
    const float* gt   = (const float*)d_in[1];
    float* out        = (float*)d_out;

    int N = in_sizes[0] / ROWF;   // 1024
    int M = in_sizes[1] / ROWF;   // 2048

    float* out_mp   = out;
    float* out_conf = out + (size_t)N * ROWF;
    float* out_idx  = out + (size_t)N * ROWF + N;

    static bool attr_set = false;  // host-side only; not in the captured graph
    if (!attr_set) {
        cudaFuncSetAttribute(pointmatcher_kernel,
                             cudaFuncAttributeMaxDynamicSharedMemorySize,
                             SMEM_BYTES);
        attr_set = true;
    }

    pointmatcher_kernel<<<N / BI, THREADS, SMEM_BYTES>>>(
        pred, gt, out_mp, out_conf, out_idx, N, M);
}